// round 5
// baseline (speedup 1.0000x reference)
#include <cuda_runtime.h>
#include <cuda_bf16.h>
#include <cstdint>

// Problem: B=8, C=512, H=W=64, P=H*W=4096
// out[b,c,h,w] = f_opt*f_sar*had^2, had = softmax_c(S_opt)*softmax_c(S_sar)
// f = W @ x (per-pixel channel mix), S[b,c] = f_bc^T f_bc (64x64)
//
// NOTE: harness compiles via virtual arch compute_103 => no tcgen05/TMEM.
// Tensor path = mma.sync HMMA (sm_80+ PTX) with bf16 split-3 for accuracy.
// X's natural [c][p] layout is K-major for the B operand -> ldmatrix.trans,
// so the fp32->bf16 hi/lo split happens in-kernel in k1 (no pre-transpose).

#define NB 8
#define NC 512
#define NP 4096
#define BR_STRIDE ((size_t)NB * NC * NP)   // floats per branch

// ---------------- scratch (static device arrays) ----------------
__device__ __align__(256) float g_f[2ull * NB * NC * NP];      // 134 MB fp32 f
__device__ __align__(256) float g_S[2ull * NB * NC * NP];      // 134 MB gram
__device__ float g_M[NB * NP];                                 // mo+ms per (b,i,j)
__device__ float g_R[NB * NP];                                 // 1/(zo*zs)
__device__ __align__(256) __nv_bfloat16 g_wh[2 * NC * NC];
__device__ __align__(256) __nv_bfloat16 g_wl[2 * NC * NC];

// ---------------- helpers ----------------
__device__ __forceinline__ uint32_t smem_u32(const void* p) {
    uint32_t a;
    asm("{ .reg .u64 t; cvta.to.shared.u64 t, %1; cvt.u32.u64 %0, t; }" : "=r"(a) : "l"(p));
    return a;
}
#define SWZ128(o) ((o) ^ (((o) >> 3) & 0x70))

#define CPA(s, g) asm volatile("cp.async.cg.shared.global [%0], [%1], 16;" :: "r"(s), "l"(g))
#define CPC()     asm volatile("cp.async.commit_group;" ::: "memory")
#define CPW(n)    asm volatile("cp.async.wait_group %0;" :: "n"(n) : "memory")

#define LDSM4(r, a) \
    asm volatile("ldmatrix.sync.aligned.m8n8.x4.shared.b16 {%0,%1,%2,%3}, [%4];" \
        : "=r"((r)[0]), "=r"((r)[1]), "=r"((r)[2]), "=r"((r)[3]) : "r"(a))

#define LDSM4T(r, a) \
    asm volatile("ldmatrix.sync.aligned.m8n8.x4.trans.shared.b16 {%0,%1,%2,%3}, [%4];" \
        : "=r"((r)[0]), "=r"((r)[1]), "=r"((r)[2]), "=r"((r)[3]) : "r"(a))

#define MMA(c, a, b0, b1) \
    asm volatile("mma.sync.aligned.m16n8k16.row.col.f32.bf16.bf16.f32 " \
        "{%0,%1,%2,%3},{%4,%5,%6,%7},{%8,%9},{%0,%1,%2,%3};" \
        : "+f"((c)[0]), "+f"((c)[1]), "+f"((c)[2]), "+f"((c)[3]) \
        : "r"((a)[0]), "r"((a)[1]), "r"((a)[2]), "r"((a)[3]), "r"(b0), "r"(b1))

// ============================================================================
// k0w: split W fp32 -> (hi, lo) bf16, same [out_c, in_c] layout
// ============================================================================
__global__ __launch_bounds__(256) void k0w(const float* __restrict__ Wo,
                                           const float* __restrict__ Ws)
{
    const int mtx = blockIdx.y;
    const float* src = mtx ? Ws : Wo;
    const int i4 = blockIdx.x * 256 + threadIdx.x;   // float4 index, 65536 total
    float4 v = ((const float4*)src)[i4];
    __nv_bfloat16 hx = __float2bfloat16(v.x), hy = __float2bfloat16(v.y);
    __nv_bfloat16 hz = __float2bfloat16(v.z), hw = __float2bfloat16(v.w);
    __nv_bfloat162* oh = (__nv_bfloat162*)(g_wh + (size_t)mtx * NC * NC);
    __nv_bfloat162* ol = (__nv_bfloat162*)(g_wl + (size_t)mtx * NC * NC);
    oh[i4 * 2]     = __nv_bfloat162(hx, hy);
    oh[i4 * 2 + 1] = __nv_bfloat162(hz, hw);
    ol[i4 * 2]     = __nv_bfloat162(__float2bfloat16(v.x - __bfloat162float(hx)),
                                    __float2bfloat16(v.y - __bfloat162float(hy)));
    ol[i4 * 2 + 1] = __nv_bfloat162(__float2bfloat16(v.z - __bfloat162float(hz)),
                                    __float2bfloat16(v.w - __bfloat162float(hw)));
}

// ============================================================================
// k1: HMMA split-3 GEMM with fused X split.
// f[z] (512 x 4096) = W'[br] (512x512) @ X[z] (512x4096)
// A = W hi/lo [m][k] bf16 row-major (cp.async, SW128, ldmatrix).
// B = raw fp32 X [k=c][n=p] tile (cp.async), split in-smem to bf16 hi/lo
//     [k][n] tiles with 272B rows, consumed via ldmatrix.trans.
// CTA 256 thr, tile M=128 N=128, K-chunk 64, double-buffered.
// grid (32 ntile, 4 mtile, 16 z)
// ============================================================================
// smem layout (bytes from base):
//   A stage s:  s*32768        (Ah at +0, Al at +16384), 2 stages = 65536
//   X stage s:  65536 + s*32768 (fp32 64x128, 512B rows), 2 stages = 65536
//   sBh:        131072          (64 x 136 bf16, 272B rows) = 17408
//   sBl:        148480          = 17408
#define K1_SMEM 165888

__global__ __launch_bounds__(256) void k1_hmma(const float* __restrict__ opt,
                                               const float* __restrict__ sar)
{
    extern __shared__ char smem[];
    const uint32_t sb = smem_u32(smem);
    const int tid = threadIdx.x;
    const int l = tid & 31, wid = tid >> 5;
    const int mwarp = wid >> 2, nwarp = wid & 3;
    const int z = blockIdx.z, br = z >> 3, b = z & 7;
    const int m0 = blockIdx.y * 128;
    const int n0 = blockIdx.x * 128;

    const __nv_bfloat16* gAh = g_wh + (size_t)br * NC * NC;
    const __nv_bfloat16* gAl = g_wl + (size_t)br * NC * NC;
    const float* Xz = (br ? sar : opt) + (size_t)b * NC * NP;

    float acc[4][4][4];
#pragma unroll
    for (int mf = 0; mf < 4; mf++)
#pragma unroll
        for (int nf = 0; nf < 4; nf++)
#pragma unroll
            for (int q = 0; q < 4; q++) acc[mf][nf][q] = 0.f;

    const int lr = tid >> 3, lq = tid & 7;

#define K1_LOAD(kt, s) do {                                                        \
    uint32_t sA_ = sb + (s) * 32768;                                               \
    uint32_t sX_ = sb + 65536 + (s) * 32768;                                       \
    _Pragma("unroll")                                                              \
    for (int it = 0; it < 4; it++) {                                               \
        int r = lr + it * 32;                                                      \
        uint32_t soff = SWZ128(r * 128 + lq * 16);                                 \
        size_t go = (size_t)(m0 + r) * NC + (kt) * 64 + lq * 8;                    \
        CPA(sA_ + soff,         gAh + go);                                         \
        CPA(sA_ + 16384 + soff, gAl + go);                                         \
    }                                                                              \
    _Pragma("unroll")                                                              \
    for (int it = 0; it < 8; it++) {                                               \
        int idx = tid + it * 256;                                                  \
        int row = idx >> 5, ch = idx & 31;                                         \
        CPA(sX_ + row * 512 + ch * 16,                                             \
            Xz + (size_t)((kt) * 64 + row) * NP + n0 + ch * 4);                    \
    }                                                                              \
    CPC();                                                                         \
} while (0)

    K1_LOAD(0, 0);

    for (int kt = 0; kt < 8; kt++) {
        const int s = kt & 1;
        if (kt < 7) { K1_LOAD(kt + 1, s ^ 1); CPW(1); }
        else        { CPW(0); }
        __syncthreads();            // A(s) + X(s) visible

        // convert fp32 X tile -> bf16 hi/lo [k][n] tiles (272B rows)
        {
            const char* sX = smem + 65536 + s * 32768;
            char* bh = smem + 131072;
            char* bl = smem + 148480;
#pragma unroll
            for (int it = 0; it < 8; it++) {
                int idx = tid + it * 256;
                int row = idx >> 5, c4 = (idx & 31) * 4;    // 4 floats
                float4 v = *(const float4*)(sX + row * 512 + c4 * 4);
                __nv_bfloat16 hx = __float2bfloat16(v.x), hy = __float2bfloat16(v.y);
                __nv_bfloat16 hz = __float2bfloat16(v.z), hw = __float2bfloat16(v.w);
                uint32_t h01 = ((uint32_t)__bfloat16_as_ushort(hy) << 16) | __bfloat16_as_ushort(hx);
                uint32_t h23 = ((uint32_t)__bfloat16_as_ushort(hw) << 16) | __bfloat16_as_ushort(hz);
                __nv_bfloat16 lx = __float2bfloat16(v.x - __bfloat162float(hx));
                __nv_bfloat16 ly = __float2bfloat16(v.y - __bfloat162float(hy));
                __nv_bfloat16 lz = __float2bfloat16(v.z - __bfloat162float(hz));
                __nv_bfloat16 lw = __float2bfloat16(v.w - __bfloat162float(hw));
                uint32_t l01 = ((uint32_t)__bfloat16_as_ushort(ly) << 16) | __bfloat16_as_ushort(lx);
                uint32_t l23 = ((uint32_t)__bfloat16_as_ushort(lw) << 16) | __bfloat16_as_ushort(lz);
                *(uint2*)(bh + row * 272 + c4 * 2) = make_uint2(h01, h23);
                *(uint2*)(bl + row * 272 + c4 * 2) = make_uint2(l01, l23);
            }
        }
        __syncthreads();            // sBh/sBl ready

        const uint32_t sA  = sb + s * 32768;
        const uint32_t sAl = sA + 16384;
        const uint32_t sBh = sb + 131072;
        const uint32_t sBl = sb + 148480;
        const int g = l >> 3;

#pragma unroll
        for (int ks = 0; ks < 4; ks++) {
            uint32_t ah[4][4], al[4][4], bh[8], bl[8];
#pragma unroll
            for (int mf = 0; mf < 4; mf++) {
                uint32_t off = (uint32_t)(mwarp * 64 + mf * 16 + (l & 15)) * 128
                             + (l >> 4) * 16 + ks * 32;
                uint32_t so = SWZ128(off);
                LDSM4(ah[mf], sA + so);
                LDSM4(al[mf], sAl + so);
            }
#pragma unroll
            for (int nf2 = 0; nf2 < 2; nf2++) {
                int row = ks * 16 + (g & 1) * 8 + (l & 7);
                int col = nwarp * 32 + nf2 * 16 + (g >> 1) * 8;
                uint32_t addr = (uint32_t)(row * 272 + col * 2);
                LDSM4T(&bh[nf2 * 4], sBh + addr);
                LDSM4T(&bl[nf2 * 4], sBl + addr);
            }
#pragma unroll
            for (int mf = 0; mf < 4; mf++)
#pragma unroll
                for (int nf = 0; nf < 4; nf++) {
                    const int bi = (nf >> 1) * 4 + (nf & 1) * 2;
                    MMA(acc[mf][nf], ah[mf], bh[bi], bh[bi + 1]);   // hi*hi
                    MMA(acc[mf][nf], al[mf], bh[bi], bh[bi + 1]);   // lo*hi
                    MMA(acc[mf][nf], ah[mf], bl[bi], bl[bi + 1]);   // hi*lo
                }
        }
        __syncthreads();            // protect sBh/sBl (next convert) + A stage
    }

    float* dst = g_f + (size_t)z * NC * NP;
    const int rbase = m0 + mwarp * 64 + (l >> 2);
    const int cbase = n0 + nwarp * 32 + (l & 3) * 2;
#pragma unroll
    for (int mf = 0; mf < 4; mf++)
#pragma unroll
        for (int nf = 0; nf < 4; nf++) {
            *(float2*)(dst + (size_t)(rbase + mf * 16) * NP + cbase + nf * 8)
                = make_float2(acc[mf][nf][0], acc[mf][nf][1]);
            *(float2*)(dst + (size_t)(rbase + mf * 16 + 8) * NP + cbase + nf * 8)
                = make_float2(acc[mf][nf][2], acc[mf][nf][3]);
        }
}

// ============================================================================
// k2: S = F^T F per (br,b,c) via HMMA split. F (fp32, 64h x 64w) read directly,
// split in-smem to bf16 hi/lo [h][w] K-major tiles; both operands via
// ldmatrix.trans. 8192 blocks, 128 threads.
// ============================================================================
__global__ __launch_bounds__(128) void k2_gram()
{
    const int blk = blockIdx.x;                       // br*4096 + b*512 + c
    const float4* F4 = (const float4*)g_f + (size_t)blk * 1024;
    float* S = g_S + (size_t)blk * NP;

    __shared__ __align__(16) __nv_bfloat16 sh[64 * 72];   // 144B rows
    __shared__ __align__(16) __nv_bfloat16 sl[64 * 72];

    const int tid = threadIdx.x;
    const int l = tid & 31, w = tid >> 5;

#pragma unroll
    for (int it = 0; it < 8; it++) {
        int f4 = tid + it * 128;                      // [0, 1024)
        float4 v = F4[f4];
        int r = f4 >> 4, c = (f4 & 15) * 4;
        __nv_bfloat16 hx = __float2bfloat16(v.x), hy = __float2bfloat16(v.y);
        __nv_bfloat16 hz = __float2bfloat16(v.z), hw = __float2bfloat16(v.w);
        uint32_t h01 = ((uint32_t)__bfloat16_as_ushort(hy) << 16) | __bfloat16_as_ushort(hx);
        uint32_t h23 = ((uint32_t)__bfloat16_as_ushort(hw) << 16) | __bfloat16_as_ushort(hz);
        __nv_bfloat16 lx = __float2bfloat16(v.x - __bfloat162float(hx));
        __nv_bfloat16 ly = __float2bfloat16(v.y - __bfloat162float(hy));
        __nv_bfloat16 lz = __float2bfloat16(v.z - __bfloat162float(hz));
        __nv_bfloat16 lw = __float2bfloat16(v.w - __bfloat162float(hw));
        uint32_t l01 = ((uint32_t)__bfloat16_as_ushort(ly) << 16) | __bfloat16_as_ushort(lx);
        uint32_t l23 = ((uint32_t)__bfloat16_as_ushort(lw) << 16) | __bfloat16_as_ushort(lz);
        *(uint2*)&sh[r * 72 + c] = make_uint2(h01, h23);
        *(uint2*)&sl[r * 72 + c] = make_uint2(l01, l23);
    }
    __syncthreads();

    const uint32_t shb = smem_u32(sh), slb = smem_u32(sl);
    const int i0 = w * 16;
    const int g = l >> 3;

    float acc[8][4];
#pragma unroll
    for (int jt = 0; jt < 8; jt++)
#pragma unroll
        for (int q = 0; q < 4; q++) acc[jt][q] = 0.f;

#pragma unroll
    for (int ks = 0; ks < 4; ks++) {
        uint32_t ah[4], al[4];
        {
            int row = ks * 16 + (g >> 1) * 8 + (l & 7);
            int col = i0 + (g & 1) * 8;
            uint32_t addr = (uint32_t)(row * 144 + col * 2);
            LDSM4T(ah, shb + addr);
            LDSM4T(al, slb + addr);
        }
        uint32_t bh[16], bl[16];
#pragma unroll
        for (int jt2 = 0; jt2 < 4; jt2++) {
            int row = ks * 16 + (g & 1) * 8 + (l & 7);
            int col = jt2 * 16 + (g >> 1) * 8;
            uint32_t addr = (uint32_t)(row * 144 + col * 2);
            LDSM4T(&bh[jt2 * 4], shb + addr);
            LDSM4T(&bl[jt2 * 4], slb + addr);
        }
#pragma unroll
        for (int jt = 0; jt < 8; jt++) {
            int bi = (jt >> 1) * 4 + (jt & 1) * 2;
            MMA(acc[jt], ah, bh[bi], bh[bi + 1]);     // hi*hi
            MMA(acc[jt], al, bh[bi], bh[bi + 1]);     // lo*hi
            MMA(acc[jt], ah, bl[bi], bl[bi + 1]);     // hi*lo
        }
    }

    const int ir = i0 + (l >> 2);
    const int jc = (l & 3) * 2;
#pragma unroll
    for (int jt = 0; jt < 8; jt++) {
        *(float2*)&S[ir * 64 + jt * 8 + jc]       = make_float2(acc[jt][0], acc[jt][1]);
        *(float2*)&S[(ir + 8) * 64 + jt * 8 + jc] = make_float2(acc[jt][2], acc[jt][3]);
    }
}

// ============================================================================
// k3: softmax stats over channel axis, both branches; emits combined M, R.
// ============================================================================
__global__ __launch_bounds__(256) void k3_stats()
{
    const int blk = blockIdx.x;
    const int b = blk >> 6, i = blk & 63;
    const int tid = threadIdx.x, j = tid & 63, cg = tid >> 6;

    const float* So = g_S + (size_t)b * NC * NP + i * 64 + j;
    const float* Ss = So + BR_STRIDE;

    float mo = -1e30f, zo = 0.f, ms = -1e30f, zs = 0.f;
    for (int c = cg * 128; c < cg * 128 + 128; c++) {
        float v = So[(size_t)c * NP];
        if (v > mo) { zo = zo * __expf(mo - v) + 1.f; mo = v; }
        else        { zo += __expf(v - mo); }
        float w = Ss[(size_t)c * NP];
        if (w > ms) { zs = zs * __expf(ms - w) + 1.f; ms = w; }
        else        { zs += __expf(w - ms); }
    }

    __shared__ float shm[2][4][64], shz[2][4][64];
    shm[0][cg][j] = mo; shz[0][cg][j] = zo;
    shm[1][cg][j] = ms; shz[1][cg][j] = zs;
    __syncthreads();

    if (cg == 0) {
        float Mo = shm[0][0][j], Ms = shm[1][0][j];
#pragma unroll
        for (int q = 1; q < 4; q++) {
            Mo = fmaxf(Mo, shm[0][q][j]);
            Ms = fmaxf(Ms, shm[1][q][j]);
        }
        float Zo = 0.f, Zs = 0.f;
#pragma unroll
        for (int q = 0; q < 4; q++) {
            Zo += shz[0][q][j] * __expf(shm[0][q][j] - Mo);
            Zs += shz[1][q][j] * __expf(shm[1][q][j] - Ms);
        }
        const int idx = b * NP + i * 64 + j;
        g_M[idx] = Mo + Ms;
        g_R[idx] = 1.0f / (Zo * Zs);
    }
}

// ============================================================================
// k4: out = f_opt*f_sar*had^2, had = exp(So+Ss-M)*R
// ============================================================================
__global__ __launch_bounds__(256) void k4_final(float* __restrict__ out)
{
    const int t = blockIdx.x * 256 + threadIdx.x;
    const int j4 = t & 15;
    const int i = (t >> 4) & 63;
    const int b = t >> 19;

    const float4 a  = ((const float4*)g_S)[t];
    const float4 bb = ((const float4*)g_S)[t + (int)(BR_STRIDE / 4)];
    const float4 fo = ((const float4*)g_f)[t];
    const float4 fs = ((const float4*)g_f)[t + (int)(BR_STRIDE / 4)];

    const int mi = b * (NP / 4) + i * 16 + j4;
    const float4 M4 = ((const float4*)g_M)[mi];
    const float4 R4 = ((const float4*)g_R)[mi];

    float4 r;
    { float had = __expf(a.x + bb.x - M4.x) * R4.x; r.x = (fo.x * fs.x) * (had * had); }
    { float had = __expf(a.y + bb.y - M4.y) * R4.y; r.y = (fo.y * fs.y) * (had * had); }
    { float had = __expf(a.z + bb.z - M4.z) * R4.z; r.z = (fo.z * fs.z) * (had * had); }
    { float had = __expf(a.w + bb.w - M4.w) * R4.w; r.w = (fo.w * fs.w) * (had * had); }
    ((float4*)out)[t] = r;
}

// ============================================================================
extern "C" void kernel_launch(void* const* d_in, const int* in_sizes, int n_in,
                              void* d_out, int out_size)
{
    const float* opt = (const float*)d_in[0];
    const float* sar = (const float*)d_in[1];
    const float* Wo  = (const float*)d_in[2];
    const float* Ws  = (const float*)d_in[3];

    cudaFuncSetAttribute(k1_hmma, cudaFuncAttributeMaxDynamicSharedMemorySize, K1_SMEM);

    k0w<<<dim3(256, 2), 256>>>(Wo, Ws);
    k1_hmma<<<dim3(32, 4, 16), 256, K1_SMEM>>>(opt, sar);
    k2_gram<<<2 * NB * NC, 128>>>();
    k3_stats<<<NB * 64, 256>>>();
    k4_final<<<16384, 256>>>((float*)d_out);
}

// round 6
// speedup vs baseline: 1.1424x; 1.1424x over previous
#include <cuda_runtime.h>
#include <cuda_bf16.h>
#include <cstdint>

// Problem: B=8, C=512, H=W=64, P=H*W=4096
// out[b,c,h,w] = f_opt*f_sar*had^2, had = softmax_c(S_opt)*softmax_c(S_sar)
// f = W @ x (per-pixel channel mix), S[b,c] = f_bc^T f_bc (64x64)
//
// NOTE: harness compiles via virtual arch compute_103 => no tcgen05/TMEM.
// Tensor path = mma.sync HMMA (sm_80+ PTX) with bf16 split-3 for accuracy.

#define NB 8
#define NC 512
#define NP 4096
#define BR_STRIDE ((size_t)NB * NC * NP)   // floats per branch

// ---------------- scratch (static device arrays) ----------------
__device__ __align__(256) float g_f[2ull * NB * NC * NP];      // 134 MB fp32 f
__device__ __align__(256) float g_S[2ull * NB * NC * NP];      // 134 MB gram
__device__ float g_M[NB * NP];                                 // mo+ms per (b,i,j)
__device__ float g_R[NB * NP];                                 // 1/(zo*zs)
// bf16-split transposed X: layout per z: [pixel 4096][channel 512]
__device__ __align__(256) __nv_bfloat16 g_xh[2ull * NB * NP * NC];
__device__ __align__(256) __nv_bfloat16 g_xl[2ull * NB * NP * NC];
__device__ __align__(256) __nv_bfloat16 g_wh[2 * NC * NC];
__device__ __align__(256) __nv_bfloat16 g_wl[2 * NC * NC];

// ---------------- helpers ----------------
__device__ __forceinline__ uint32_t smem_u32(const void* p) {
    uint32_t a;
    asm("{ .reg .u64 t; cvta.to.shared.u64 t, %1; cvt.u32.u64 %0, t; }" : "=r"(a) : "l"(p));
    return a;
}
#define SWZ128(o) ((o) ^ (((o) >> 3) & 0x70))

#define CPA(s, g) asm volatile("cp.async.cg.shared.global [%0], [%1], 16;" :: "r"(s), "l"(g))
#define CPC()     asm volatile("cp.async.commit_group;" ::: "memory")
#define CPW(n)    asm volatile("cp.async.wait_group %0;" :: "n"(n) : "memory")

#define LDSM4(r, a) \
    asm volatile("ldmatrix.sync.aligned.m8n8.x4.shared.b16 {%0,%1,%2,%3}, [%4];" \
        : "=r"((r)[0]), "=r"((r)[1]), "=r"((r)[2]), "=r"((r)[3]) : "r"(a))

#define LDSM4T(r, a) \
    asm volatile("ldmatrix.sync.aligned.m8n8.x4.trans.shared.b16 {%0,%1,%2,%3}, [%4];" \
        : "=r"((r)[0]), "=r"((r)[1]), "=r"((r)[2]), "=r"((r)[3]) : "r"(a))

#define MMA(c, a, b0, b1) \
    asm volatile("mma.sync.aligned.m16n8k16.row.col.f32.bf16.bf16.f32 " \
        "{%0,%1,%2,%3},{%4,%5,%6,%7},{%8,%9},{%0,%1,%2,%3};" \
        : "+f"((c)[0]), "+f"((c)[1]), "+f"((c)[2]), "+f"((c)[3]) \
        : "r"((a)[0]), "r"((a)[1]), "r"((a)[2]), "r"((a)[3]), "r"(b0), "r"(b1))

// split a float4 into packed bf16x2 hi/lo words
__device__ __forceinline__ void split4(float4 v, uint2& h, uint2& lo) {
    __nv_bfloat16 hx = __float2bfloat16(v.x), hy = __float2bfloat16(v.y);
    __nv_bfloat16 hz = __float2bfloat16(v.z), hw = __float2bfloat16(v.w);
    h.x = ((uint32_t)__bfloat16_as_ushort(hy) << 16) | __bfloat16_as_ushort(hx);
    h.y = ((uint32_t)__bfloat16_as_ushort(hw) << 16) | __bfloat16_as_ushort(hz);
    __nv_bfloat16 lx = __float2bfloat16(v.x - __bfloat162float(hx));
    __nv_bfloat16 ly = __float2bfloat16(v.y - __bfloat162float(hy));
    __nv_bfloat16 lz = __float2bfloat16(v.z - __bfloat162float(hz));
    __nv_bfloat16 lw = __float2bfloat16(v.w - __bfloat162float(hw));
    lo.x = ((uint32_t)__bfloat16_as_ushort(ly) << 16) | __bfloat16_as_ushort(lx);
    lo.y = ((uint32_t)__bfloat16_as_ushort(lw) << 16) | __bfloat16_as_ushort(lz);
}

// ============================================================================
// k0w: split W fp32 -> (hi, lo) bf16, same [out_c, in_c] layout
// ============================================================================
__global__ __launch_bounds__(256) void k0w(const float* __restrict__ Wo,
                                           const float* __restrict__ Ws)
{
    const int mtx = blockIdx.y;
    const float* src = mtx ? Ws : Wo;
    const int i4 = blockIdx.x * 256 + threadIdx.x;
    float4 v = ((const float4*)src)[i4];
    uint2 h, lo;
    split4(v, h, lo);
    ((uint2*)(g_wh + (size_t)mtx * NC * NC))[i4] = h;
    ((uint2*)(g_wl + (size_t)mtx * NC * NC))[i4] = lo;
}

// ============================================================================
// k0x: transpose + split X: [c 512][p 4096] fp32 -> Xt hi/lo [p 4096][c 512] bf16
// ============================================================================
__global__ __launch_bounds__(256) void k0x(const float* __restrict__ opt,
                                           const float* __restrict__ sar)
{
    const int z = blockIdx.z;
    const int br = z >> 3, b = z & 7;
    const float* X = (br ? sar : opt) + (size_t)b * NC * NP;
    const int p0 = blockIdx.x * 64, c0 = blockIdx.y * 64;
    const int tid = threadIdx.x;

    __shared__ float t[64][65];
#pragma unroll
    for (int it = 0; it < 4; it++) {
        int f4 = tid + it * 256;
        int r = f4 >> 4, q = f4 & 15;
        float4 v = *(const float4*)(X + (size_t)(c0 + r) * NP + p0 + q * 4);
        t[r][q * 4 + 0] = v.x; t[r][q * 4 + 1] = v.y;
        t[r][q * 4 + 2] = v.z; t[r][q * 4 + 3] = v.w;
    }
    __syncthreads();

#pragma unroll
    for (int it = 0; it < 8; it++) {
        int u = tid + it * 256;
        int pr = u >> 5, c2 = u & 31;
        int c = c2 * 2;
        float v0 = t[c][pr], v1 = t[c + 1][pr];
        __nv_bfloat16 h0 = __float2bfloat16(v0), h1 = __float2bfloat16(v1);
        size_t idx2 = ((size_t)z * NP * NC + (size_t)(p0 + pr) * NC + (c0 + c)) >> 1;
        ((__nv_bfloat162*)g_xh)[idx2] = __nv_bfloat162(h0, h1);
        ((__nv_bfloat162*)g_xl)[idx2] =
            __nv_bfloat162(__float2bfloat16(v0 - __bfloat162float(h0)),
                           __float2bfloat16(v1 - __bfloat162float(h1)));
    }
}

// ============================================================================
// k1: HMMA split-3 GEMM (round-4 proven config).
// f[z] (512 x 4096) = W'[br] (512x512) @ X[z] (512x4096)
// ============================================================================
#define K1_STAGE 65536                 // Ah 16K | Al 16K | Bh 16K | Bl 16K
#define K1_SMEM  (2 * K1_STAGE)

__global__ __launch_bounds__(256) void k1_hmma()
{
    extern __shared__ char smem[];
    const uint32_t sb = smem_u32(smem);
    const int tid = threadIdx.x;
    const int l = tid & 31, wid = tid >> 5;
    const int mwarp = wid >> 2, nwarp = wid & 3;
    const int z = blockIdx.z, br = z >> 3;
    const int m0 = blockIdx.y * 128;
    const int n0 = blockIdx.x * 128;

    const __nv_bfloat16* gAh = g_wh + (size_t)br * NC * NC;
    const __nv_bfloat16* gAl = g_wl + (size_t)br * NC * NC;
    const __nv_bfloat16* gBh = g_xh + (size_t)z * NP * NC;
    const __nv_bfloat16* gBl = g_xl + (size_t)z * NP * NC;

    float acc[4][4][4];
#pragma unroll
    for (int mf = 0; mf < 4; mf++)
#pragma unroll
        for (int nf = 0; nf < 4; nf++)
#pragma unroll
            for (int q = 0; q < 4; q++) acc[mf][nf][q] = 0.f;

    const int lr = tid >> 3, lq = tid & 7;

#define K1_LOAD(kt, s) do {                                                        \
    uint32_t sbase = sb + (s) * K1_STAGE;                                          \
    _Pragma("unroll")                                                              \
    for (int it = 0; it < 4; it++) {                                               \
        int r = lr + it * 32;                                                      \
        uint32_t soff = SWZ128(r * 128 + lq * 16);                                 \
        size_t go = (size_t)r * NC + (kt) * 64 + lq * 8;                           \
        CPA(sbase + soff,         gAh + (size_t)m0 * NC + go);                     \
        CPA(sbase + 16384 + soff, gAl + (size_t)m0 * NC + go);                     \
        CPA(sbase + 32768 + soff, gBh + (size_t)n0 * NC + go);                     \
        CPA(sbase + 49152 + soff, gBl + (size_t)n0 * NC + go);                     \
    }                                                                              \
    CPC();                                                                         \
} while (0)

    K1_LOAD(0, 0);

    for (int kt = 0; kt < 8; kt++) {
        const int s = kt & 1;
        if (kt < 7) { K1_LOAD(kt + 1, s ^ 1); CPW(1); }
        else        { CPW(0); }
        __syncthreads();

        const uint32_t sA  = sb + s * K1_STAGE;
        const uint32_t sAl = sA + 16384;
        const uint32_t sB  = sA + 32768;
        const uint32_t sBl = sA + 49152;

#pragma unroll
        for (int ks = 0; ks < 4; ks++) {
            uint32_t ah[4][4], al[4][4], bh[8], bl[8];
#pragma unroll
            for (int mf = 0; mf < 4; mf++) {
                uint32_t off = (uint32_t)(mwarp * 64 + mf * 16 + (l & 15)) * 128
                             + (l >> 4) * 16 + ks * 32;
                uint32_t so = SWZ128(off);
                LDSM4(ah[mf], sA + so);
                LDSM4(al[mf], sAl + so);
            }
#pragma unroll
            for (int nf2 = 0; nf2 < 2; nf2++) {
                uint32_t off = (uint32_t)(nwarp * 32 + nf2 * 16 + (l & 7) + ((l >> 4) << 3)) * 128
                             + ((l >> 3) & 1) * 16 + ks * 32;
                uint32_t so = SWZ128(off);
                LDSM4(&bh[nf2 * 4], sB + so);
                LDSM4(&bl[nf2 * 4], sBl + so);
            }
#pragma unroll
            for (int mf = 0; mf < 4; mf++)
#pragma unroll
                for (int nf = 0; nf < 4; nf++) {
                    const int bi = (nf >> 1) * 4 + (nf & 1) * 2;
                    MMA(acc[mf][nf], ah[mf], bh[bi], bh[bi + 1]);   // hi*hi
                    MMA(acc[mf][nf], al[mf], bh[bi], bh[bi + 1]);   // lo*hi
                    MMA(acc[mf][nf], ah[mf], bl[bi], bl[bi + 1]);   // hi*lo
                }
        }
        __syncthreads();
    }

    float* dst = g_f + (size_t)z * NC * NP;
    const int rbase = m0 + mwarp * 64 + (l >> 2);
    const int cbase = n0 + nwarp * 32 + (l & 3) * 2;
#pragma unroll
    for (int mf = 0; mf < 4; mf++)
#pragma unroll
        for (int nf = 0; nf < 4; nf++) {
            *(float2*)(dst + (size_t)(rbase + mf * 16) * NP + cbase + nf * 8)
                = make_float2(acc[mf][nf][0], acc[mf][nf][1]);
            *(float2*)(dst + (size_t)(rbase + mf * 16 + 8) * NP + cbase + nf * 8)
                = make_float2(acc[mf][nf][2], acc[mf][nf][3]);
        }
}

// ============================================================================
// k2: S = F^T F per (br,b,c) via HMMA split (round-4 proven, 51.7us).
// ============================================================================
__global__ __launch_bounds__(128) void k2_gram()
{
    const int blk = blockIdx.x;                       // br*4096 + b*512 + c
    const float4* F4 = (const float4*)g_f + (size_t)blk * 1024;
    float* S = g_S + (size_t)blk * NP;

    __shared__ __align__(16) __nv_bfloat16 sh[64 * 72];   // 144B rows
    __shared__ __align__(16) __nv_bfloat16 sl[64 * 72];

    const int tid = threadIdx.x;
    const int l = tid & 31, w = tid >> 5;

#pragma unroll
    for (int it = 0; it < 8; it++) {
        int f4 = tid + it * 128;
        float4 v = F4[f4];
        int r = f4 >> 4, c = (f4 & 15) * 4;
        uint2 h, lo;
        split4(v, h, lo);
        *(uint2*)&sh[r * 72 + c] = h;
        *(uint2*)&sl[r * 72 + c] = lo;
    }
    __syncthreads();

    const uint32_t shb = smem_u32(sh), slb = smem_u32(sl);
    const int i0 = w * 16;
    const int g = l >> 3;

    float acc[8][4];
#pragma unroll
    for (int jt = 0; jt < 8; jt++)
#pragma unroll
        for (int q = 0; q < 4; q++) acc[jt][q] = 0.f;

#pragma unroll
    for (int ks = 0; ks < 4; ks++) {
        uint32_t ah[4], al[4];
        {
            int row = ks * 16 + (g >> 1) * 8 + (l & 7);
            int col = i0 + (g & 1) * 8;
            uint32_t addr = (uint32_t)(row * 144 + col * 2);
            LDSM4T(ah, shb + addr);
            LDSM4T(al, slb + addr);
        }
        uint32_t bh[16], bl[16];
#pragma unroll
        for (int jt2 = 0; jt2 < 4; jt2++) {
            int row = ks * 16 + (g & 1) * 8 + (l & 7);
            int col = jt2 * 16 + (g >> 1) * 8;
            uint32_t addr = (uint32_t)(row * 144 + col * 2);
            LDSM4T(&bh[jt2 * 4], shb + addr);
            LDSM4T(&bl[jt2 * 4], slb + addr);
        }
#pragma unroll
        for (int jt = 0; jt < 8; jt++) {
            int bi = (jt >> 1) * 4 + (jt & 1) * 2;
            MMA(acc[jt], ah, bh[bi], bh[bi + 1]);     // hi*hi
            MMA(acc[jt], al, bh[bi], bh[bi + 1]);     // lo*hi
            MMA(acc[jt], ah, bl[bi], bl[bi + 1]);     // hi*lo
        }
    }

    const int ir = i0 + (l >> 2);
    const int jc = (l & 3) * 2;
#pragma unroll
    for (int jt = 0; jt < 8; jt++) {
        *(float2*)&S[ir * 64 + jt * 8 + jc]       = make_float2(acc[jt][0], acc[jt][1]);
        *(float2*)&S[(ir + 8) * 64 + jt * 8 + jc] = make_float2(acc[jt][2], acc[jt][3]);
    }
}

// ============================================================================
// k3: softmax stats, branch-free chunked, float4-vectorized.
// Block per (b,i): 512 blocks, 256 threads: j4 = t&15 (4 j's), cg = t>>4
// (16 groups x 32 c). Chunks of 8 c: chunk-max then exp-sum. smem merge.
// ============================================================================
__global__ __launch_bounds__(256) void k3_stats()
{
    const int blk = blockIdx.x;
    const int b = blk >> 6, i = blk & 63;
    const int t = threadIdx.x, j4 = t & 15, cg = t >> 4;

    const float4* So = (const float4*)g_S + ((size_t)b * NC + cg * 32) * 1024 + i * 16 + j4;
    const float4* Ss = So + BR_STRIDE / 4;

    float4 mo = make_float4(-1e30f, -1e30f, -1e30f, -1e30f), ms = mo;
    float4 zo = make_float4(0.f, 0.f, 0.f, 0.f), zs = zo;

#pragma unroll
    for (int ch = 0; ch < 4; ch++) {
        float4 vo[8], vs[8];
#pragma unroll
        for (int k = 0; k < 8; k++) {
            vo[k] = So[(size_t)(ch * 8 + k) * 1024];
            vs[k] = Ss[(size_t)(ch * 8 + k) * 1024];
        }
        float4 cmo = vo[0], cms = vs[0];
#pragma unroll
        for (int k = 1; k < 8; k++) {
            cmo.x = fmaxf(cmo.x, vo[k].x); cmo.y = fmaxf(cmo.y, vo[k].y);
            cmo.z = fmaxf(cmo.z, vo[k].z); cmo.w = fmaxf(cmo.w, vo[k].w);
            cms.x = fmaxf(cms.x, vs[k].x); cms.y = fmaxf(cms.y, vs[k].y);
            cms.z = fmaxf(cms.z, vs[k].z); cms.w = fmaxf(cms.w, vs[k].w);
        }
        float4 nmo, nms;
        nmo.x = fmaxf(mo.x, cmo.x); nmo.y = fmaxf(mo.y, cmo.y);
        nmo.z = fmaxf(mo.z, cmo.z); nmo.w = fmaxf(mo.w, cmo.w);
        nms.x = fmaxf(ms.x, cms.x); nms.y = fmaxf(ms.y, cms.y);
        nms.z = fmaxf(ms.z, cms.z); nms.w = fmaxf(ms.w, cms.w);
        zo.x *= __expf(mo.x - nmo.x); zo.y *= __expf(mo.y - nmo.y);
        zo.z *= __expf(mo.z - nmo.z); zo.w *= __expf(mo.w - nmo.w);
        zs.x *= __expf(ms.x - nms.x); zs.y *= __expf(ms.y - nms.y);
        zs.z *= __expf(ms.z - nms.z); zs.w *= __expf(ms.w - nms.w);
        mo = nmo; ms = nms;
#pragma unroll
        for (int k = 0; k < 8; k++) {
            zo.x += __expf(vo[k].x - mo.x); zo.y += __expf(vo[k].y - mo.y);
            zo.z += __expf(vo[k].z - mo.z); zo.w += __expf(vo[k].w - mo.w);
            zs.x += __expf(vs[k].x - ms.x); zs.y += __expf(vs[k].y - ms.y);
            zs.z += __expf(vs[k].z - ms.z); zs.w += __expf(vs[k].w - ms.w);
        }
    }

    __shared__ float4 smo[16][16], szo[16][16], sms[16][16], szs[16][16];
    smo[cg][j4] = mo; szo[cg][j4] = zo;
    sms[cg][j4] = ms; szs[cg][j4] = zs;
    __syncthreads();

    if (t < 16) {
        float4 Mo = smo[0][t], Ms = sms[0][t];
#pragma unroll
        for (int gq = 1; gq < 16; gq++) {
            float4 a = smo[gq][t], c = sms[gq][t];
            Mo.x = fmaxf(Mo.x, a.x); Mo.y = fmaxf(Mo.y, a.y);
            Mo.z = fmaxf(Mo.z, a.z); Mo.w = fmaxf(Mo.w, a.w);
            Ms.x = fmaxf(Ms.x, c.x); Ms.y = fmaxf(Ms.y, c.y);
            Ms.z = fmaxf(Ms.z, c.z); Ms.w = fmaxf(Ms.w, c.w);
        }
        float4 Zo = make_float4(0.f, 0.f, 0.f, 0.f), Zs = Zo;
#pragma unroll
        for (int gq = 0; gq < 16; gq++) {
            float4 a = smo[gq][t], za = szo[gq][t];
            float4 c = sms[gq][t], zc = szs[gq][t];
            Zo.x += za.x * __expf(a.x - Mo.x); Zo.y += za.y * __expf(a.y - Mo.y);
            Zo.z += za.z * __expf(a.z - Mo.z); Zo.w += za.w * __expf(a.w - Mo.w);
            Zs.x += zc.x * __expf(c.x - Ms.x); Zs.y += zc.y * __expf(c.y - Ms.y);
            Zs.z += zc.z * __expf(c.z - Ms.z); Zs.w += zc.w * __expf(c.w - Ms.w);
        }
        const int mi = b * (NP / 4) + i * 16 + t;
        ((float4*)g_M)[mi] = make_float4(Mo.x + Ms.x, Mo.y + Ms.y, Mo.z + Ms.z, Mo.w + Ms.w);
        ((float4*)g_R)[mi] = make_float4(1.f / (Zo.x * Zs.x), 1.f / (Zo.y * Zs.y),
                                         1.f / (Zo.z * Zs.z), 1.f / (Zo.w * Zs.w));
    }
}

// ============================================================================
// k4': fused gram-recompute + final. Block per (b,c): 4096 blocks, 128 thr.
// Loads Fo, Fs (both branches), recomputes So, Ss via the k2 HMMA-split path,
// reads M/R, forms out = fo*fs*had^2, stages in smem, coalesced float4 store.
// Eliminates k4's S-read (268MB) and f-read (268MB).
// smem: sh_o 9216 | sl_o 9216 | sh_s 9216 | sl_s 9216 | stage 64x68 f32 17408
// ============================================================================
#define K4_SMEM (4 * 9216 + 64 * 68 * 4)

__global__ __launch_bounds__(128) void k4_fused(float* __restrict__ out)
{
    extern __shared__ char smem[];
    __nv_bfloat16* sh_o = (__nv_bfloat16*)smem;
    __nv_bfloat16* sl_o = (__nv_bfloat16*)(smem + 9216);
    __nv_bfloat16* sh_s = (__nv_bfloat16*)(smem + 18432);
    __nv_bfloat16* sl_s = (__nv_bfloat16*)(smem + 27648);
    float* stage = (float*)(smem + 36864);                // [64][68]

    const int blk = blockIdx.x;                           // b*512 + c
    const int b = blk >> 9;
    const float4* Fo4 = (const float4*)g_f + (size_t)blk * 1024;
    const float4* Fs4 = Fo4 + BR_STRIDE / 4;

    const int tid = threadIdx.x;
    const int l = tid & 31, w = tid >> 5;

    // load + split both branches' F tiles
#pragma unroll
    for (int it = 0; it < 8; it++) {
        int f4 = tid + it * 128;
        int r = f4 >> 4, c = (f4 & 15) * 4;
        uint2 h, lo;
        split4(Fo4[f4], h, lo);
        *(uint2*)&sh_o[r * 72 + c] = h;
        *(uint2*)&sl_o[r * 72 + c] = lo;
        split4(Fs4[f4], h, lo);
        *(uint2*)&sh_s[r * 72 + c] = h;
        *(uint2*)&sl_s[r * 72 + c] = lo;
    }
    __syncthreads();

    const uint32_t sho = smem_u32(sh_o), slo = smem_u32(sl_o);
    const uint32_t shs = smem_u32(sh_s), sls = smem_u32(sl_s);
    const int i0 = w * 16;
    const int g = l >> 3;

    float ao[8][4], as_[8][4];
#pragma unroll
    for (int jt = 0; jt < 8; jt++)
#pragma unroll
        for (int q = 0; q < 4; q++) { ao[jt][q] = 0.f; as_[jt][q] = 0.f; }

#pragma unroll
    for (int ks = 0; ks < 4; ks++) {
        const int arow = ks * 16 + (g >> 1) * 8 + (l & 7);
        const int acol = i0 + (g & 1) * 8;
        const uint32_t aaddr = (uint32_t)(arow * 144 + acol * 2);
        const int brow = ks * 16 + (g & 1) * 8 + (l & 7);

        // branch OPT
        {
            uint32_t ah[4], al[4], bh[16], bl[16];
            LDSM4T(ah, sho + aaddr);
            LDSM4T(al, slo + aaddr);
#pragma unroll
            for (int jt2 = 0; jt2 < 4; jt2++) {
                uint32_t addr = (uint32_t)(brow * 144 + (jt2 * 16 + (g >> 1) * 8) * 2);
                LDSM4T(&bh[jt2 * 4], sho + addr);
                LDSM4T(&bl[jt2 * 4], slo + addr);
            }
#pragma unroll
            for (int jt = 0; jt < 8; jt++) {
                int bi = (jt >> 1) * 4 + (jt & 1) * 2;
                MMA(ao[jt], ah, bh[bi], bh[bi + 1]);
                MMA(ao[jt], al, bh[bi], bh[bi + 1]);
                MMA(ao[jt], ah, bl[bi], bl[bi + 1]);
            }
        }
        // branch SAR
        {
            uint32_t ah[4], al[4], bh[16], bl[16];
            LDSM4T(ah, shs + aaddr);
            LDSM4T(al, sls + aaddr);
#pragma unroll
            for (int jt2 = 0; jt2 < 4; jt2++) {
                uint32_t addr = (uint32_t)(brow * 144 + (jt2 * 16 + (g >> 1) * 8) * 2);
                LDSM4T(&bh[jt2 * 4], shs + addr);
                LDSM4T(&bl[jt2 * 4], sls + addr);
            }
#pragma unroll
            for (int jt = 0; jt < 8; jt++) {
                int bi = (jt >> 1) * 4 + (jt & 1) * 2;
                MMA(as_[jt], ah, bh[bi], bh[bi + 1]);
                MMA(as_[jt], al, bh[bi], bh[bi + 1]);
                MMA(as_[jt], ah, bl[bi], bl[bi + 1]);
            }
        }
    }

    // epilogue: had = exp(So+Ss-M)*R; out = fo*fs*had^2 -> stage
    const float* gM = g_M + (size_t)b * NP;
    const float* gR = g_R + (size_t)b * NP;
    const int jc = (l & 3) * 2;
#pragma unroll
    for (int jt = 0; jt < 8; jt++) {
        const int j = jt * 8 + jc;
#pragma unroll
        for (int half = 0; half < 2; half++) {
            const int i = i0 + (l >> 2) + half * 8;
            float2 M2 = *(const float2*)(gM + i * 64 + j);
            float2 R2 = *(const float2*)(gR + i * 64 + j);
            // reconstruct fo, fs at (i, j), (i, j+1) from hi+lo tiles
            float2 foh = __bfloat1622float2(*(__nv_bfloat162*)&sh_o[i * 72 + j]);
            float2 fol = __bfloat1622float2(*(__nv_bfloat162*)&sl_o[i * 72 + j]);
            float2 fsh = __bfloat1622float2(*(__nv_bfloat162*)&sh_s[i * 72 + j]);
            float2 fsl = __bfloat1622float2(*(__nv_bfloat162*)&sl_s[i * 72 + j]);
            float fo0 = foh.x + fol.x, fo1 = foh.y + fol.y;
            float fs0 = fsh.x + fsl.x, fs1 = fsh.y + fsl.y;
            float so0 = ao[jt][half * 2], so1 = ao[jt][half * 2 + 1];
            float ss0 = as_[jt][half * 2], ss1 = as_[jt][half * 2 + 1];
            float h0 = __expf(so0 + ss0 - M2.x) * R2.x;
            float h1 = __expf(so1 + ss1 - M2.y) * R2.y;
            *(float2*)&stage[i * 68 + j] =
                make_float2((fo0 * fs0) * (h0 * h0), (fo1 * fs1) * (h1 * h1));
        }
    }
    __syncthreads();

    // coalesced store: 64 rows x 16 float4
    float4* o4 = (float4*)out + (size_t)blk * 1024;
#pragma unroll
    for (int it = 0; it < 8; it++) {
        int idx = tid + it * 128;
        int r = idx >> 4, c4 = idx & 15;
        o4[idx] = *(float4*)&stage[r * 68 + c4 * 4];
    }
}

// ============================================================================
extern "C" void kernel_launch(void* const* d_in, const int* in_sizes, int n_in,
                              void* d_out, int out_size)
{
    const float* opt = (const float*)d_in[0];
    const float* sar = (const float*)d_in[1];
    const float* Wo  = (const float*)d_in[2];
    const float* Ws  = (const float*)d_in[3];

    cudaFuncSetAttribute(k1_hmma, cudaFuncAttributeMaxDynamicSharedMemorySize, K1_SMEM);
    cudaFuncSetAttribute(k4_fused, cudaFuncAttributeMaxDynamicSharedMemorySize, K4_SMEM);

    k0w<<<dim3(256, 2), 256>>>(Wo, Ws);
    k0x<<<dim3(64, 8, 16), 256>>>(opt, sar);
    k1_hmma<<<dim3(32, 4, 16), 256, K1_SMEM>>>();
    k2_gram<<<2 * NB * NC, 128>>>();
    k3_stats<<<NB * 64, 256>>>();
    k4_fused<<<NB * NC, 128, K4_SMEM>>>((float*)d_out);
}